// round 12
// baseline (speedup 1.0000x reference)
#include <cuda_runtime.h>
#include <cuda_fp16.h>

#define DINLINE __device__ __forceinline__
typedef unsigned int u32;
typedef unsigned short u16;

constexpr int B_ = 8, T_ = 64, N_ = 512, H_ = 128, E_ = 8192;
constexpr int S_ = B_ * N_;       // 4096 sequences
constexpr int G1_ = 128, G2_ = 64;
constexpr int G4H = 4 * H_;       // 512 gate rows

// ---------------- SMEM layout (byte offsets) -----------------------------------
constexpr int WROW    = 272;                   // 136 fp16 per row (128 + 8 pad)
constexpr int OFF_W   = 0;                     // 512*272 = 139264
constexpr int OFF_H   = 139264;                // h planes (2 x 32 x 272), fp16
constexpr int HPLANE  = 32 * WROW;             // 8704
constexpr int OFF_SX  = OFF_H + 2 * HPLANE;    // 156672 (MODE 0 only): 8192 B
constexpr int REC_SM  = OFF_SX + 8192;         // 164864

constexpr int OFF_AH  = 139264;                // proj: A plane 128*272
constexpr int APLANE  = 128 * WROW;            // 34816
constexpr int PROJ_SM = OFF_AH + APLANE;       // 174080

// ---------------- device scratch (static globals; no allocation) ---------------
__device__ __half g_hh [(size_t)T_ * S_ * H_];   // [t*S+s][j]    64 MiB
__device__ __half g_xph[(size_t)T_ * S_ * G4H];  // [t*S+s][4j+g] 256 MiB
__device__ u32   g_whh_h[3][G4H * 64];           // permuted fp16-pair W_hh
__device__ u32   g_wih_h[2][G4H * 64];           // permuted fp16-pair W_ih
__device__ float g_br[3][G4H];                   // b_ih+b_hh permuted (4j+g)
__device__ float g_w0r[G4H];                     // w_ih0 permuted
__device__ float g_xl1[S_ * G1_];
__device__ float g_h1[S_ * G1_];
__device__ float g_xl2[S_ * G2_];
__device__ float g_h2[S_ * G2_];
__device__ float g_dis[N_];
__device__ int   g_is64;

// ---------------- helpers -------------------------------------------------------
DINLINE float tanhfast(float x) {
    float y;
    asm("tanh.approx.f32 %0, %1;" : "=f"(y) : "f"(x));
    return y;
}

DINLINE u32 smem_u32(const void* p) {
    u32 a;
    asm("{ .reg .u64 t; cvta.to.shared.u64 t, %1; cvt.u32.u64 %0, t; }" : "=r"(a) : "l"(p));
    return a;
}

DINLINE void mma_f16(float* D, const u32* A, u32 b0, u32 b1) {
    asm("mma.sync.aligned.m16n8k16.row.col.f32.f16.f16.f32 "
        "{%0,%1,%2,%3},{%4,%5,%6,%7},{%8,%9},{%0,%1,%2,%3};"
        : "+f"(D[0]), "+f"(D[1]), "+f"(D[2]), "+f"(D[3])
        : "r"(A[0]), "r"(A[1]), "r"(A[2]), "r"(A[3]), "r"(b0), "r"(b1));
}

#define LDSM4(R, ADDR) \
    asm volatile("ldmatrix.sync.aligned.m8n8.x4.shared.b16 {%0,%1,%2,%3},[%4];" \
        : "=r"((R)[0]), "=r"((R)[1]), "=r"((R)[2]), "=r"((R)[3]) : "r"(ADDR))

#define STSM2(ADDR, R0, R1) \
    asm volatile("stmatrix.sync.aligned.m8n8.x2.shared.b16 [%0], {%1,%2};" \
        :: "r"(ADDR), "r"(R0), "r"(R1))

DINLINE u32 packh(float a, float b) {
    __half2 h = __floats2half2_rn(a, b);
    return *(u32*)&h;
}

DINLINE int edge_at(const void* p, int is64, int idx) {
    return is64 ? (int)((const long long*)p)[idx] : ((const int*)p)[idx];
}

// ---------------- fused edge prep: dtype detect + degree + rsqrt ----------------
__global__ void k_edge_prep(const void* __restrict__ ei) {
    __shared__ float sdeg[N_];
    __shared__ int nz;
    const int tid = threadIdx.x;   // 512 threads
    if (tid == 0) nz = 0;
    sdeg[tid] = 1.0f;              // self-loop
    __syncthreads();
    const int* ei32 = (const int*)ei;
    int acc = 0;
    for (int i = 1 + 2 * tid; i < 2 * E_; i += 1024) acc |= ei32[i];
    if (acc) atomicOr(&nz, 1);
    __syncthreads();
    int is64 = (nz == 0) ? 1 : 0;
    if (tid == 0) g_is64 = is64;
    for (int e = tid; e < E_; e += 512)
        atomicAdd(&sdeg[edge_at(ei, is64, E_ + e)], 1.0f);
    __syncthreads();
    g_dis[tid] = rsqrtf(sdeg[tid]);
}

// ---------------- weight prep: permute rows (4j+g), fp16-pair pack --------------
__global__ void k_prep_w(const float* __restrict__ w, u32* __restrict__ outw) {
    int i = blockIdx.x * blockDim.x + threadIdx.x;   // 512*64
    int colp = i >> 6, kp = i & 63;
    int j = colp >> 2, g = colp & 3;
    const float* wr = w + (g * H_ + j) * H_ + 2 * kp;
    outw[i] = packh(wr[0], wr[1]);
}

__global__ void k_prep_b(const float* __restrict__ bi, const float* __restrict__ bh,
                         float* __restrict__ outb) {
    int colp = blockIdx.x * blockDim.x + threadIdx.x;
    if (colp < G4H) {
        int j = colp >> 2, g = colp & 3;
        outb[colp] = bi[g * H_ + j] + bh[g * H_ + j];
    }
}

__global__ void k_prep_bw0(const float* __restrict__ bi, const float* __restrict__ bh,
                           const float* __restrict__ w) {
    int colp = blockIdx.x * blockDim.x + threadIdx.x;
    if (colp < G4H) {
        int j = colp >> 2, g = colp & 3;
        g_br[0][colp] = bi[g * H_ + j] + bh[g * H_ + j];
        g_w0r[colp]   = w[g * H_ + j];
    }
}

// ---------------- gate fold: shuffle, input add, activations; returns h ----------
template <int MODE>
DINLINE float gate_fold(float* D, float& c_ref, const char* sm, bool evn,
                        int myrow, int t, uint2 xq, uint2 wh, uint2 bh) {
    float sv0 = evn ? D[2] : D[0];
    float rr0 = __shfl_xor_sync(0xffffffffu, sv0, 1);
    float sv1 = evn ? D[3] : D[1];
    float rr1 = __shfl_xor_sync(0xffffffffu, sv1, 1);
    float pi = evn ? D[0] : rr0;
    float pf = evn ? D[1] : rr1;
    float pg = evn ? rr0 : D[2];
    float po = evn ? rr1 : D[3];

    if (MODE == 1) {
        float2 fa = __half22float2(*(__half2*)&xq.x);
        float2 fb = __half22float2(*(__half2*)&xq.y);
        pi += fa.x; pf += fa.y; pg += fb.x; po += fb.y;
    } else {
        float xv = ((const float*)(sm + OFF_SX))[t * 32 + myrow];
        float2 wa = __half22float2(*(__half2*)&wh.x);
        float2 wb = __half22float2(*(__half2*)&wh.y);
        float2 ba = __half22float2(*(__half2*)&bh.x);
        float2 bb = __half22float2(*(__half2*)&bh.y);
        pi += xv * wa.x + ba.x;
        pf += xv * wa.y + ba.y;
        pg += xv * wb.x + bb.x;
        po += xv * wb.y + bb.y;
    }

    float si = fmaf(tanhfast(0.5f * pi), 0.5f, 0.5f);
    float sf = fmaf(tanhfast(0.5f * pf), 0.5f, 0.5f);
    float so = fmaf(tanhfast(0.5f * po), 0.5f, 0.5f);
    float cn = sf * c_ref + si * tanhfast(pg);
    c_ref = cn;
    return so * tanhfast(cn);
}

// ---------------- tensor-core LSTM recurrence ------------------------------------
// 512 threads, 16 warps. Warp w owns gate-cols [32w, 32w+32) for BOTH m-tiles;
// B fragments resident in 64 regs. h written via stmatrix (one STSM.x2 per mt).
template <int MODE, int WRITE_ALL>
__global__ void __launch_bounds__(512, 1) rec_mma(
    const float* __restrict__ x,               // MODE 0
    const u32* __restrict__ w_h,               // [512][64] fp16 pairs
    const float* __restrict__ w0r,             // MODE 0
    const float* __restrict__ br0)             // MODE 0
{
    extern __shared__ __align__(16) char sm[];
    const u32 sbase = smem_u32(sm);

    const int tid = threadIdx.x, wid = tid >> 5, lane = tid & 31;
    const int grp = lane >> 2, tid4 = lane & 3;
    const bool evn = (tid4 & 1) == 0;           // rowA holders (tid4 in {0,2})
    const int cw = wid;                          // 32-col group
    const int s0 = blockIdx.x * 32;

    for (int i = tid; i < 512 * 64; i += 512) {
        int r = i >> 6, c = i & 63;
        *(u32*)(sm + OFF_W + r * WROW + c * 4) = w_h[i];
    }
    for (int i = tid; i < HPLANE / 4; i += 512)       // zero plane 0
        ((u32*)(sm + OFF_H))[i] = 0;
    if (MODE == 0) {
        float* sx = (float*)(sm + OFF_SX);
        for (int i = tid; i < 64 * 32; i += 512) {
            int t = i >> 5, m = i & 31;
            int s = s0 + m;
            sx[i] = x[(s >> 9) * (T_ * N_) + t * N_ + (s & (N_ - 1))];
        }
    }
    __syncthreads();

    const int qa = lane >> 3;
    const int a_loff = ((lane & 7) + (qa & 1) * 8) * WROW + ((qa >> 1) * 8) * 2;
    const int b_loff = (lane & 7) * WROW + qa * 16;
    const int rowoff = evn ? grp : grp + 8;
    // stmatrix row address component (lanes 0-15 meaningful)
    const int st_row = (lane & 15);
    const int st_loff = st_row * WROW + cw * 16;

    // resident B fragments: 4 n-tiles x 8 ks x 2 regs = 64 regs
    u32 breg[4][8][2];
#pragma unroll
    for (int nt = 0; nt < 4; nt++) {
        const int n0 = cw * 32 + nt * 8;
#pragma unroll
        for (int kc = 0; kc < 4; kc++) {
            u32 r[4];
            LDSM4(r, sbase + OFF_W + n0 * WROW + b_loff + kc * 64);
            breg[nt][kc * 2][0] = r[0]; breg[nt][kc * 2][1] = r[1];
            breg[nt][kc * 2 + 1][0] = r[2]; breg[nt][kc * 2 + 1][1] = r[3];
        }
    }

    // MODE 0: loop-invariant w0/bias as fp16 registers (j = cw*8+nt*2+(tid4>>1))
    uint2 whr[4], bhr[4];
    if (MODE == 0) {
#pragma unroll
        for (int nt = 0; nt < 4; nt++) {
            int j = cw * 8 + nt * 2 + (tid4 >> 1);
            float4 w4 = ((const float4*)w0r)[j];
            float4 b4 = ((const float4*)br0)[j];
            whr[nt] = make_uint2(packh(w4.x, w4.y), packh(w4.z, w4.w));
            bhr[nt] = make_uint2(packh(b4.x, b4.y), packh(b4.z, b4.w));
        }
    }

    float c_st[8];
#pragma unroll
    for (int q = 0; q < 8; q++) c_st[q] = 0.0f;

    for (int t = 0; t < T_; t++) {
        const int rb = t & 1, wb = rb ^ 1;
        const int hw_off = OFF_H + wb * HPLANE;
        const u32 st_base = sbase + hw_off + st_loff;

#pragma unroll
        for (int mt = 0; mt < 2; mt++) {
            const int myrow = mt * 16 + rowoff;

            // prefetch xp for this m-tile (self-consumed)
            uint2 xq[4];
            if (MODE == 1) {
                const __half* xpb = g_xph + ((size_t)t * S_ + s0 + myrow) * G4H
                                    + cw * 32 + (tid4 >> 1) * 4;
#pragma unroll
                for (int nt = 0; nt < 4; nt++)
                    xq[nt] = *(const uint2*)(xpb + nt * 8);
            }

            float D[4][4];
#pragma unroll
            for (int nt = 0; nt < 4; nt++)
#pragma unroll
                for (int q = 0; q < 4; q++) D[nt][q] = 0.0f;

            const u32 a_base = sbase + OFF_H + rb * HPLANE + mt * 16 * WROW + a_loff;
#pragma unroll
            for (int kchunk = 0; kchunk < 2; kchunk++) {
                u32 ahi[4][4];
#pragma unroll
                for (int k4 = 0; k4 < 4; k4++)
                    LDSM4(ahi[k4], a_base + (kchunk * 4 + k4) * 32);
#pragma unroll
                for (int nt = 0; nt < 4; nt++)
#pragma unroll
                    for (int k4 = 0; k4 < 4; k4++)
                        mma_f16(D[nt], ahi[k4],
                                breg[nt][kchunk * 4 + k4][0],
                                breg[nt][kchunk * 4 + k4][1]);
            }

            float hv[4];
#pragma unroll
            for (int nt = 0; nt < 4; nt++)
                hv[nt] = gate_fold<MODE>(D[nt], c_st[mt * 4 + nt], sm, evn, myrow,
                                         t, xq[nt], whr[nt], bhr[nt]);

            // pack col pairs: partner across tid4^2 holds the other col parity
            u32 pk[4];
#pragma unroll
            for (int c = 0; c < 4; c++) {
                float o = __shfl_xor_sync(0xffffffffu, hv[c], 2);
                pk[c] = (tid4 < 2) ? packh(hv[c], o) : packh(o, hv[c]);
            }
            // row-group exchange: send pk[tid4^1], keep pk[tid4]
            u32 own, send;
            own  = (tid4 & 2) ? ((tid4 & 1) ? pk[3] : pk[2])
                              : ((tid4 & 1) ? pk[1] : pk[0]);
            send = (tid4 & 2) ? ((tid4 & 1) ? pk[2] : pk[3])
                              : ((tid4 & 1) ? pk[0] : pk[1]);
            u32 recv = __shfl_xor_sync(0xffffffffu, send, 1);
            u32 reg0 = evn ? own  : recv;   // rows 0-7 tile
            u32 reg1 = evn ? recv : own;    // rows 8-15 tile
            STSM2(st_base + mt * 16 * WROW, reg0, reg1);
        }

        __syncthreads();   // h(wb) complete; A-reads of rb done

        if (WRITE_ALL || t == T_ - 1) {
            for (int i = tid; i < 32 * 32; i += 512) {
                int r = i >> 5, jp4 = i & 31;
                uint2 v = *(const uint2*)(sm + hw_off + r * WROW + jp4 * 8);
                *(uint2*)&g_hh[((size_t)t * S_ + s0 + r) * H_ + jp4 * 4] = v;
            }
        }
    }
}

// ---------------- tensor-core input projection (persistent, 512 thr) -------------
__global__ void __launch_bounds__(512, 1) proj_mma(
    const u32* __restrict__ w_h,
    const float* __restrict__ br)
{
    extern __shared__ __align__(16) char sm[];
    const u32 sbase = smem_u32(sm);

    const int tid = threadIdx.x, wid = tid >> 5, lane = tid & 31;
    const int grp = lane >> 2, tid4 = lane & 3;
    const int cw = wid;

    for (int i = tid; i < 512 * 64; i += 512) {
        int r = i >> 6, c = i & 63;
        *(u32*)(sm + OFF_W + r * WROW + c * 4) = w_h[i];
    }
    __syncthreads();

    const int qa = lane >> 3;
    const int a_loff = ((lane & 7) + (qa & 1) * 8) * WROW + ((qa >> 1) * 8) * 2;
    const int b_loff = (lane & 7) * WROW + qa * 16;

    u32 breg[4][8][2];
    float2 bbv[4];
#pragma unroll
    for (int nt = 0; nt < 4; nt++) {
        const int n0 = cw * 32 + nt * 8;
#pragma unroll
        for (int kc = 0; kc < 4; kc++) {
            u32 r[4];
            LDSM4(r, sbase + OFF_W + n0 * WROW + b_loff + kc * 64);
            breg[nt][kc * 2][0] = r[0]; breg[nt][kc * 2][1] = r[1];
            breg[nt][kc * 2 + 1][0] = r[2]; breg[nt][kc * 2 + 1][1] = r[3];
        }
        bbv[nt] = *(const float2*)&br[n0 + tid4 * 2];
    }

    const int ntiles = (T_ * S_) / 128;   // 2048
    for (int rt = blockIdx.x; rt < ntiles; rt += gridDim.x) {
        __syncthreads();
        const u32* src = (const u32*)(g_hh + (size_t)rt * 128 * H_);
        for (int i = tid; i < 128 * 64; i += 512) {
            int row = i >> 6, kp = i & 63;
            *(u32*)(sm + OFF_AH + row * WROW + kp * 4) = src[i];
        }
        __syncthreads();

#pragma unroll 1
        for (int mt = 0; mt < 8; mt++) {
            u32 ahi[8][4];
            const u32 abase = sbase + OFF_AH + mt * 16 * WROW + a_loff;
#pragma unroll
            for (int ks = 0; ks < 8; ks++) LDSM4(ahi[ks], abase + ks * 32);

#pragma unroll
            for (int nt = 0; nt < 4; nt++) {
                const int n0 = cw * 32 + nt * 8;
                float D[4] = {bbv[nt].x, bbv[nt].y, bbv[nt].x, bbv[nt].y};
#pragma unroll
                for (int ks = 0; ks < 8; ks++)
                    mma_f16(D, ahi[ks], breg[nt][ks][0], breg[nt][ks][1]);

                size_t rowA = ((size_t)rt * 128 + mt * 16 + grp) * G4H;
                size_t rowB = rowA + 8 * G4H;
                *(u32*)&g_xph[rowA + n0 + tid4 * 2] = packh(D[0], D[1]);
                *(u32*)&g_xph[rowB + n0 + tid4 * 2] = packh(D[2], D[3]);
            }
        }
    }
}

// ---------------- GCN -------------------------------------------------------------
__global__ void k_lin1(const float* __restrict__ w, const float* __restrict__ bias) {
    __shared__ float fr[8][H_];
    int r0 = blockIdx.x * 8, tid = threadIdx.x;   // 512 blocks, 128 thr
    for (int i = tid; i < 8 * H_; i += 128) {
        int r = i >> 7, k = i & 127;
        fr[r][k] = __half2float(g_hh[((size_t)(T_ - 1) * S_ + r0 + r) * H_ + k]);
    }
    __syncthreads();
    const float* wr = w + tid * H_;
    float acc[8] = {0, 0, 0, 0, 0, 0, 0, 0};
#pragma unroll 4
    for (int k = 0; k < H_; k++) {
        float wk = wr[k];
#pragma unroll
        for (int r = 0; r < 8; r++) acc[r] = fmaf(fr[r][k], wk, acc[r]);
    }
    float bv = bias[tid];
#pragma unroll
    for (int r = 0; r < 8; r++) {
        g_xl1[(r0 + r) * G1_ + tid] = acc[r];
        float d = g_dis[(r0 + r) & (N_ - 1)];
        g_h1[(r0 + r) * G1_ + tid] = bv + acc[r] * d * d;
    }
}

__global__ void k_lin2(const float* __restrict__ w, const float* __restrict__ bias) {
    __shared__ float fr[8][G1_];
    int r0 = blockIdx.x * 8, tid = threadIdx.x;   // 512 blocks, 64 thr
    for (int i = tid; i < 8 * G1_; i += 64) {
        int r = i >> 7, k = i & 127;
        fr[r][k] = fmaxf(g_h1[(r0 + r) * G1_ + k], 0.0f);
    }
    __syncthreads();
    const float* wr = w + tid * G1_;
    float acc[8] = {0, 0, 0, 0, 0, 0, 0, 0};
#pragma unroll 4
    for (int k = 0; k < G1_; k++) {
        float wk = wr[k];
#pragma unroll
        for (int r = 0; r < 8; r++) acc[r] = fmaf(fr[r][k], wk, acc[r]);
    }
    float bv = bias[tid];
#pragma unroll
    for (int r = 0; r < 8; r++) {
        g_xl2[(r0 + r) * G2_ + tid] = acc[r];
        float d = g_dis[(r0 + r) & (N_ - 1)];
        g_h2[(r0 + r) * G2_ + tid] = bv + acc[r] * d * d;
    }
}

template <int Gd>
__global__ void k_agg_edge(const void* __restrict__ ei) {
    constexpr int G4 = Gd / 4;
    const float* xl = (Gd == G1_) ? g_xl1 : g_xl2;
    float* outb     = (Gd == G1_) ? g_h1  : g_h2;
    int i = blockIdx.x * blockDim.x + threadIdx.x;
    constexpr int per = B_ * G4;
    if (i >= E_ * per) return;
    int e = i / per;
    int r = i - e * per;
    int b = r / G4;
    int g4 = r - b * G4;
    int is64 = g_is64;
    int src = edge_at(ei, is64, e);
    int dst = edge_at(ei, is64, E_ + e);
    float norm = g_dis[src] * g_dis[dst];
    float4 v = *(const float4*)&xl[(b * N_ + src) * Gd + g4 * 4];
    float* o = &outb[(b * N_ + dst) * Gd + g4 * 4];
    atomicAdd(o + 0, v.x * norm);
    atomicAdd(o + 1, v.y * norm);
    atomicAdd(o + 2, v.z * norm);
    atomicAdd(o + 3, v.w * norm);
}

__global__ void k_final(const float* __restrict__ cls_w,
                        const float* __restrict__ cls_b,
                        float* __restrict__ out) {
    int b = blockIdx.x, tid = threadIdx.x;
    __shared__ float red[256];
    float a = 0.0f;
    for (int i = tid; i < N_ * G2_; i += 256) {
        int g = i & (G2_ - 1);
        a = fmaf(fmaxf(g_h2[b * (N_ * G2_) + i], 0.0f), cls_w[g], a);
    }
    red[tid] = a;
    __syncthreads();
    for (int s = 128; s > 0; s >>= 1) {
        if (tid < s) red[tid] += red[tid + s];
        __syncthreads();
    }
    if (tid == 0) out[b] = red[0] * (1.0f / N_) + cls_b[0];
}

// ---------------- launch -----------------------------------------------------------
extern "C" void kernel_launch(void* const* d_in, const int* in_sizes, int n_in,
                              void* d_out, int out_size) {
    const float* x      = (const float*)d_in[0];
    const void*  ei     = d_in[1];
    const float* w_ih0  = (const float*)d_in[2];
    const float* w_hh0  = (const float*)d_in[3];
    const float* b_ih0  = (const float*)d_in[4];
    const float* b_hh0  = (const float*)d_in[5];
    const float* w_ih1  = (const float*)d_in[6];
    const float* w_hh1  = (const float*)d_in[7];
    const float* b_ih1  = (const float*)d_in[8];
    const float* b_hh1  = (const float*)d_in[9];
    const float* w_ih2  = (const float*)d_in[10];
    const float* w_hh2  = (const float*)d_in[11];
    const float* b_ih2  = (const float*)d_in[12];
    const float* b_hh2  = (const float*)d_in[13];
    const float* gcn1_w = (const float*)d_in[14];
    const float* gcn1_b = (const float*)d_in[15];
    const float* gcn2_w = (const float*)d_in[16];
    const float* gcn2_b = (const float*)d_in[17];
    const float* cls_w  = (const float*)d_in[18];
    const float* cls_b  = (const float*)d_in[19];
    float* out = (float*)d_out;

    u32 *whh, *wih;
    float *br, *w0r;
    cudaGetSymbolAddress((void**)&whh, g_whh_h);
    cudaGetSymbolAddress((void**)&wih, g_wih_h);
    cudaGetSymbolAddress((void**)&br, g_br);
    cudaGetSymbolAddress((void**)&w0r, g_w0r);

    cudaFuncSetAttribute(rec_mma<0, 1>, cudaFuncAttributeMaxDynamicSharedMemorySize, REC_SM);
    cudaFuncSetAttribute(rec_mma<1, 1>, cudaFuncAttributeMaxDynamicSharedMemorySize, REC_SM);
    cudaFuncSetAttribute(rec_mma<1, 0>, cudaFuncAttributeMaxDynamicSharedMemorySize, REC_SM);
    cudaFuncSetAttribute(proj_mma, cudaFuncAttributeMaxDynamicSharedMemorySize, PROJ_SM);

    constexpr int WN = G4H * 64;
    const int RB = S_ / 32;   // 128 blocks

    // layer 0
    k_edge_prep<<<1, 512>>>(ei);
    k_prep_w<<<WN / 256, 256>>>(w_hh0, whh + 0 * WN);
    k_prep_bw0<<<2, 256>>>(b_ih0, b_hh0, w_ih0);
    rec_mma<0, 1><<<RB, 512, REC_SM>>>(x, whh + 0 * WN, w0r, br + 0 * G4H);

    // layer 1
    k_prep_w<<<WN / 256, 256>>>(w_ih1, wih + 0 * WN);
    k_prep_b<<<2, 256>>>(b_ih1, b_hh1, br + 1 * G4H);
    proj_mma<<<148, 512, PROJ_SM>>>(wih + 0 * WN, br + 1 * G4H);
    k_prep_w<<<WN / 256, 256>>>(w_hh1, whh + 1 * WN);
    rec_mma<1, 1><<<RB, 512, REC_SM>>>(nullptr, whh + 1 * WN, nullptr, nullptr);

    // layer 2
    k_prep_w<<<WN / 256, 256>>>(w_ih2, wih + 1 * WN);
    k_prep_b<<<2, 256>>>(b_ih2, b_hh2, br + 2 * G4H);
    proj_mma<<<148, 512, PROJ_SM>>>(wih + 1 * WN, br + 2 * G4H);
    k_prep_w<<<WN / 256, 256>>>(w_hh2, whh + 2 * WN);
    rec_mma<1, 0><<<RB, 512, REC_SM>>>(nullptr, whh + 2 * WN, nullptr, nullptr);

    // GCN
    k_lin1<<<S_ / 8, 128>>>(gcn1_w, gcn1_b);
    k_agg_edge<G1_><<<(E_ * B_ * (G1_ / 4) + 255) / 256, 256>>>(ei);
    k_lin2<<<S_ / 8, 64>>>(gcn2_w, gcn2_b);
    k_agg_edge<G2_><<<(E_ * B_ * (G2_ / 4) + 255) / 256, 256>>>(ei);
    k_final<<<B_, 256>>>(cls_w, cls_b, out);
}

// round 13
// speedup vs baseline: 1.0079x; 1.0079x over previous
#include <cuda_runtime.h>
#include <cuda_fp16.h>

#define DINLINE __device__ __forceinline__
typedef unsigned int u32;
typedef unsigned short u16;

constexpr int B_ = 8, T_ = 64, N_ = 512, H_ = 128, E_ = 8192;
constexpr int S_ = B_ * N_;       // 4096 sequences
constexpr int G1_ = 128, G2_ = 64;
constexpr int G4H = 4 * H_;       // 512 gate rows

// ---------------- SMEM layout (byte offsets) -----------------------------------
constexpr int WROW    = 272;                   // 136 fp16 per row (128 + 8 pad)
constexpr int OFF_W   = 0;                     // 512*272 = 139264
constexpr int OFF_H   = 139264;                // h planes (2 x 32 x 272), fp16
constexpr int HPLANE  = 32 * WROW;             // 8704
constexpr int OFF_SX  = OFF_H + 2 * HPLANE;    // 156672 (MODE 0 only): 8192 B
constexpr int REC_SM  = OFF_SX + 8192;         // 164864

constexpr int OFF_AH  = 139264;                // proj: A plane 128*272
constexpr int APLANE  = 128 * WROW;            // 34816
constexpr int PROJ_SM = OFF_AH + APLANE;       // 174080

// ---------------- device scratch (static globals; no allocation) ---------------
__device__ __half g_hh [(size_t)T_ * S_ * H_];   // [t*S+s][j]    64 MiB
__device__ __half g_xph[(size_t)T_ * S_ * G4H];  // [t*S+s][4j+g] 256 MiB
__device__ u32   g_whh_h[3][G4H * 64];           // permuted fp16-pair W_hh
__device__ u32   g_wih_h[2][G4H * 64];           // permuted fp16-pair W_ih
__device__ float g_br[3][G4H];                   // b_ih+b_hh permuted (4j+g)
__device__ float g_w0r[G4H];                     // w_ih0 permuted
__device__ float g_xl1[S_ * G1_];
__device__ float g_h1[S_ * G1_];
__device__ float g_xl2[S_ * G2_];
__device__ float g_h2[S_ * G2_];
__device__ float g_dis[N_];
__device__ int   g_is64;

// ---------------- helpers -------------------------------------------------------
DINLINE u32 h2tanh(u32 x) {
    u32 y;
    asm("tanh.approx.f16x2 %0, %1;" : "=r"(y) : "r"(x));
    return y;
}

DINLINE u32 smem_u32(const void* p) {
    u32 a;
    asm("{ .reg .u64 t; cvta.to.shared.u64 t, %1; cvt.u32.u64 %0, t; }" : "=r"(a) : "l"(p));
    return a;
}

DINLINE void mma_f16(float* D, const u32* A, u32 b0, u32 b1) {
    asm("mma.sync.aligned.m16n8k16.row.col.f32.f16.f16.f32 "
        "{%0,%1,%2,%3},{%4,%5,%6,%7},{%8,%9},{%0,%1,%2,%3};"
        : "+f"(D[0]), "+f"(D[1]), "+f"(D[2]), "+f"(D[3])
        : "r"(A[0]), "r"(A[1]), "r"(A[2]), "r"(A[3]), "r"(b0), "r"(b1));
}

#define LDSM4(R, ADDR) \
    asm volatile("ldmatrix.sync.aligned.m8n8.x4.shared.b16 {%0,%1,%2,%3},[%4];" \
        : "=r"((R)[0]), "=r"((R)[1]), "=r"((R)[2]), "=r"((R)[3]) : "r"(ADDR))

DINLINE u32 packh(float a, float b) {
    __half2 h = __floats2half2_rn(a, b);
    return *(u32*)&h;
}

DINLINE int edge_at(const void* p, int is64, int idx) {
    return is64 ? (int)((const long long*)p)[idx] : ((const int*)p)[idx];
}

// ---------------- fused edge prep: dtype detect + degree + rsqrt ----------------
__global__ void k_edge_prep(const void* __restrict__ ei) {
    __shared__ float sdeg[N_];
    __shared__ int nz;
    const int tid = threadIdx.x;   // 512 threads
    if (tid == 0) nz = 0;
    sdeg[tid] = 1.0f;              // self-loop
    __syncthreads();
    const int* ei32 = (const int*)ei;
    int acc = 0;
    for (int i = 1 + 2 * tid; i < 2 * E_; i += 1024) acc |= ei32[i];
    if (acc) atomicOr(&nz, 1);
    __syncthreads();
    int is64 = (nz == 0) ? 1 : 0;
    if (tid == 0) g_is64 = is64;
    for (int e = tid; e < E_; e += 512)
        atomicAdd(&sdeg[edge_at(ei, is64, E_ + e)], 1.0f);
    __syncthreads();
    g_dis[tid] = rsqrtf(sdeg[tid]);
}

// ---------------- weight prep: permute rows (4j+g), fp16-pair pack --------------
__global__ void k_prep_w(const float* __restrict__ w, u32* __restrict__ outw) {
    int i = blockIdx.x * blockDim.x + threadIdx.x;   // 512*64
    int colp = i >> 6, kp = i & 63;
    int j = colp >> 2, g = colp & 3;
    const float* wr = w + (g * H_ + j) * H_ + 2 * kp;
    outw[i] = packh(wr[0], wr[1]);
}

__global__ void k_prep_b(const float* __restrict__ bi, const float* __restrict__ bh,
                         float* __restrict__ outb) {
    int colp = blockIdx.x * blockDim.x + threadIdx.x;
    if (colp < G4H) {
        int j = colp >> 2, g = colp & 3;
        outb[colp] = bi[g * H_ + j] + bh[g * H_ + j];
    }
}

__global__ void k_prep_bw0(const float* __restrict__ bi, const float* __restrict__ bh,
                           const float* __restrict__ w) {
    int colp = blockIdx.x * blockDim.x + threadIdx.x;
    if (colp < G4H) {
        int j = colp >> 2, g = colp & 3;
        g_br[0][colp] = bi[g * H_ + j] + bh[g * H_ + j];
        g_w0r[colp]   = w[g * H_ + j];
    }
}

// ---------------- gate pre: shuffle, input add, f16x2 activations ----------------
// Produces output-gate sigmoid (so) and new cell state (cn); tanh(cn) is batched
// by the caller across cell pairs.
template <int MODE>
DINLINE void gate_pre(const float* D, float& c_ref, const char* sm, bool evn,
                      int myrow, int t, uint2 xq, uint2 wh, uint2 bh,
                      float& so_o, float& cn_o) {
    float sv0 = evn ? D[2] : D[0];
    float rr0 = __shfl_xor_sync(0xffffffffu, sv0, 1);
    float sv1 = evn ? D[3] : D[1];
    float rr1 = __shfl_xor_sync(0xffffffffu, sv1, 1);
    float pi = evn ? D[0] : rr0;
    float pf = evn ? D[1] : rr1;
    float pg = evn ? rr0 : D[2];
    float po = evn ? rr1 : D[3];

    if (MODE == 1) {
        float2 fa = __half22float2(*(__half2*)&xq.x);
        float2 fb = __half22float2(*(__half2*)&xq.y);
        pi += fa.x; pf += fa.y; pg += fb.x; po += fb.y;
    } else {
        float xv = ((const float*)(sm + OFF_SX))[t * 32 + myrow];
        float2 wa = __half22float2(*(__half2*)&wh.x);
        float2 wb = __half22float2(*(__half2*)&wh.y);
        float2 ba = __half22float2(*(__half2*)&bh.x);
        float2 bb = __half22float2(*(__half2*)&bh.y);
        pi += xv * wa.x + ba.x;
        pf += xv * wa.y + ba.y;
        pg += xv * wb.x + bb.x;
        po += xv * wb.y + bb.y;
    }

    u32 ta = h2tanh(packh(0.5f * pi, 0.5f * pf));   // (tanh(pi/2), tanh(pf/2))
    u32 tb = h2tanh(packh(pg, 0.5f * po));          // (tanh(pg), tanh(po/2))
    float2 fa = __half22float2(*(__half2*)&ta);
    float2 fb = __half22float2(*(__half2*)&tb);
    float si = fmaf(fa.x, 0.5f, 0.5f);
    float sf = fmaf(fa.y, 0.5f, 0.5f);
    so_o = fmaf(fb.y, 0.5f, 0.5f);
    float cnv = sf * c_ref + si * fb.x;
    c_ref = cnv;
    cn_o = cnv;
}

// ---------------- tensor-core LSTM recurrence ------------------------------------
// 512 threads, 16 warps. Warp w owns gate-cols [32w, 32w+32) for BOTH m-tiles;
// B fragments resident in 64 regs. h written via scalar STS.16 (R11 layout).
template <int MODE, int WRITE_ALL>
__global__ void __launch_bounds__(512, 1) rec_mma(
    const float* __restrict__ x,               // MODE 0
    const u32* __restrict__ w_h,               // [512][64] fp16 pairs
    const float* __restrict__ w0r,             // MODE 0
    const float* __restrict__ br0)             // MODE 0
{
    extern __shared__ __align__(16) char sm[];
    const u32 sbase = smem_u32(sm);

    const int tid = threadIdx.x, wid = tid >> 5, lane = tid & 31;
    const int grp = lane >> 2, tid4 = lane & 3;
    const bool evn = (tid4 & 1) == 0;
    const int cw = wid;                        // 32-col group
    const int s0 = blockIdx.x * 32;

    for (int i = tid; i < 512 * 64; i += 512) {
        int r = i >> 6, c = i & 63;
        *(u32*)(sm + OFF_W + r * WROW + c * 4) = w_h[i];
    }
    for (int i = tid; i < HPLANE / 4; i += 512)       // zero plane 0
        ((u32*)(sm + OFF_H))[i] = 0;
    if (MODE == 0) {
        float* sx = (float*)(sm + OFF_SX);
        for (int i = tid; i < 64 * 32; i += 512) {
            int t = i >> 5, m = i & 31;
            int s = s0 + m;
            sx[i] = x[(s >> 9) * (T_ * N_) + t * N_ + (s & (N_ - 1))];
        }
    }
    __syncthreads();

    const int qa = lane >> 3;
    const int a_loff = ((lane & 7) + (qa & 1) * 8) * WROW + ((qa >> 1) * 8) * 2;
    const int b_loff = (lane & 7) * WROW + qa * 16;
    const int rowoff = evn ? grp : grp + 8;

    // resident B fragments: 4 n-tiles x 8 ks x 2 regs = 64 regs
    u32 breg[4][8][2];
#pragma unroll
    for (int nt = 0; nt < 4; nt++) {
        const int n0 = cw * 32 + nt * 8;
#pragma unroll
        for (int kc = 0; kc < 4; kc++) {
            u32 r[4];
            LDSM4(r, sbase + OFF_W + n0 * WROW + b_loff + kc * 64);
            breg[nt][kc * 2][0] = r[0]; breg[nt][kc * 2][1] = r[1];
            breg[nt][kc * 2 + 1][0] = r[2]; breg[nt][kc * 2 + 1][1] = r[3];
        }
    }

    // MODE 0: loop-invariant w0/bias as fp16 registers (j = cw*8+nt*2+(tid4>>1))
    uint2 whr[4], bhr[4];
    if (MODE == 0) {
#pragma unroll
        for (int nt = 0; nt < 4; nt++) {
            int j = cw * 8 + nt * 2 + (tid4 >> 1);
            float4 w4 = ((const float4*)w0r)[j];
            float4 b4 = ((const float4*)br0)[j];
            whr[nt] = make_uint2(packh(w4.x, w4.y), packh(w4.z, w4.w));
            bhr[nt] = make_uint2(packh(b4.x, b4.y), packh(b4.z, b4.w));
        }
    }

    float c_st[8];
#pragma unroll
    for (int q = 0; q < 8; q++) c_st[q] = 0.0f;

    for (int t = 0; t < T_; t++) {
        const int rb = t & 1, wb = rb ^ 1;
        const int hw_off = OFF_H + wb * HPLANE;

#pragma unroll
        for (int mt = 0; mt < 2; mt++) {
            const int myrow = mt * 16 + rowoff;

            // prefetch xp for this m-tile (self-consumed)
            uint2 xq[4];
            if (MODE == 1) {
                const __half* xpb = g_xph + ((size_t)t * S_ + s0 + myrow) * G4H
                                    + cw * 32 + (tid4 >> 1) * 4;
#pragma unroll
                for (int nt = 0; nt < 4; nt++)
                    xq[nt] = *(const uint2*)(xpb + nt * 8);
            }

            float D[4][4];
#pragma unroll
            for (int nt = 0; nt < 4; nt++)
#pragma unroll
                for (int q = 0; q < 4; q++) D[nt][q] = 0.0f;

            const u32 a_base = sbase + OFF_H + rb * HPLANE + mt * 16 * WROW + a_loff;
#pragma unroll
            for (int kchunk = 0; kchunk < 2; kchunk++) {
                u32 ahi[4][4];
#pragma unroll
                for (int k4 = 0; k4 < 4; k4++)
                    LDSM4(ahi[k4], a_base + (kchunk * 4 + k4) * 32);
#pragma unroll
                for (int nt = 0; nt < 4; nt++)
#pragma unroll
                    for (int k4 = 0; k4 < 4; k4++)
                        mma_f16(D[nt], ahi[k4],
                                breg[nt][kchunk * 4 + k4][0],
                                breg[nt][kchunk * 4 + k4][1]);
            }

            float so[4], cn[4];
#pragma unroll
            for (int nt = 0; nt < 4; nt++)
                gate_pre<MODE>(D[nt], c_st[mt * 4 + nt], sm, evn, myrow,
                               t, xq[nt], whr[nt], bhr[nt], so[nt], cn[nt]);

            // batched tanh(cn) across cell pairs
            u32 tc0 = h2tanh(packh(cn[0], cn[1]));
            u32 tc1 = h2tanh(packh(cn[2], cn[3]));
            float2 f0 = __half22float2(*(__half2*)&tc0);
            float2 f1 = __half22float2(*(__half2*)&tc1);
            float hv[4] = {so[0] * f0.x, so[1] * f0.y, so[2] * f1.x, so[3] * f1.y};

#pragma unroll
            for (int nt = 0; nt < 4; nt++) {
                int j = cw * 8 + nt * 2 + (tid4 >> 1);
                *(__half*)(sm + hw_off + myrow * WROW + j * 2) = __float2half_rn(hv[nt]);
            }
        }

        __syncthreads();   // h(wb) complete; A-reads of rb done

        if (WRITE_ALL || t == T_ - 1) {
            for (int i = tid; i < 32 * 32; i += 512) {
                int r = i >> 5, jp4 = i & 31;
                uint2 v = *(const uint2*)(sm + hw_off + r * WROW + jp4 * 8);
                *(uint2*)&g_hh[((size_t)t * S_ + s0 + r) * H_ + jp4 * 4] = v;
            }
        }
    }
}

// ---------------- tensor-core input projection (persistent, 512 thr) -------------
__global__ void __launch_bounds__(512, 1) proj_mma(
    const u32* __restrict__ w_h,
    const float* __restrict__ br)
{
    extern __shared__ __align__(16) char sm[];
    const u32 sbase = smem_u32(sm);

    const int tid = threadIdx.x, wid = tid >> 5, lane = tid & 31;
    const int grp = lane >> 2, tid4 = lane & 3;
    const int cw = wid;

    for (int i = tid; i < 512 * 64; i += 512) {
        int r = i >> 6, c = i & 63;
        *(u32*)(sm + OFF_W + r * WROW + c * 4) = w_h[i];
    }
    __syncthreads();

    const int qa = lane >> 3;
    const int a_loff = ((lane & 7) + (qa & 1) * 8) * WROW + ((qa >> 1) * 8) * 2;
    const int b_loff = (lane & 7) * WROW + qa * 16;

    u32 breg[4][8][2];
    float2 bbv[4];
#pragma unroll
    for (int nt = 0; nt < 4; nt++) {
        const int n0 = cw * 32 + nt * 8;
#pragma unroll
        for (int kc = 0; kc < 4; kc++) {
            u32 r[4];
            LDSM4(r, sbase + OFF_W + n0 * WROW + b_loff + kc * 64);
            breg[nt][kc * 2][0] = r[0]; breg[nt][kc * 2][1] = r[1];
            breg[nt][kc * 2 + 1][0] = r[2]; breg[nt][kc * 2 + 1][1] = r[3];
        }
        bbv[nt] = *(const float2*)&br[n0 + tid4 * 2];
    }

    const int ntiles = (T_ * S_) / 128;   // 2048
    for (int rt = blockIdx.x; rt < ntiles; rt += gridDim.x) {
        __syncthreads();
        const u32* src = (const u32*)(g_hh + (size_t)rt * 128 * H_);
        for (int i = tid; i < 128 * 64; i += 512) {
            int row = i >> 6, kp = i & 63;
            *(u32*)(sm + OFF_AH + row * WROW + kp * 4) = src[i];
        }
        __syncthreads();

#pragma unroll 1
        for (int mt = 0; mt < 8; mt++) {
            u32 ahi[8][4];
            const u32 abase = sbase + OFF_AH + mt * 16 * WROW + a_loff;
#pragma unroll
            for (int ks = 0; ks < 8; ks++) LDSM4(ahi[ks], abase + ks * 32);

#pragma unroll
            for (int nt = 0; nt < 4; nt++) {
                const int n0 = cw * 32 + nt * 8;
                float D[4] = {bbv[nt].x, bbv[nt].y, bbv[nt].x, bbv[nt].y};
#pragma unroll
                for (int ks = 0; ks < 8; ks++)
                    mma_f16(D, ahi[ks], breg[nt][ks][0], breg[nt][ks][1]);

                size_t rowA = ((size_t)rt * 128 + mt * 16 + grp) * G4H;
                size_t rowB = rowA + 8 * G4H;
                *(u32*)&g_xph[rowA + n0 + tid4 * 2] = packh(D[0], D[1]);
                *(u32*)&g_xph[rowB + n0 + tid4 * 2] = packh(D[2], D[3]);
            }
        }
    }
}

// ---------------- GCN -------------------------------------------------------------
__global__ void k_lin1(const float* __restrict__ w, const float* __restrict__ bias) {
    __shared__ float fr[8][H_];
    int r0 = blockIdx.x * 8, tid = threadIdx.x;   // 512 blocks, 128 thr
    for (int i = tid; i < 8 * H_; i += 128) {
        int r = i >> 7, k = i & 127;
        fr[r][k] = __half2float(g_hh[((size_t)(T_ - 1) * S_ + r0 + r) * H_ + k]);
    }
    __syncthreads();
    const float* wr = w + tid * H_;
    float acc[8] = {0, 0, 0, 0, 0, 0, 0, 0};
#pragma unroll 4
    for (int k = 0; k < H_; k++) {
        float wk = wr[k];
#pragma unroll
        for (int r = 0; r < 8; r++) acc[r] = fmaf(fr[r][k], wk, acc[r]);
    }
    float bv = bias[tid];
#pragma unroll
    for (int r = 0; r < 8; r++) {
        g_xl1[(r0 + r) * G1_ + tid] = acc[r];
        float d = g_dis[(r0 + r) & (N_ - 1)];
        g_h1[(r0 + r) * G1_ + tid] = bv + acc[r] * d * d;
    }
}

__global__ void k_lin2(const float* __restrict__ w, const float* __restrict__ bias) {
    __shared__ float fr[8][G1_];
    int r0 = blockIdx.x * 8, tid = threadIdx.x;   // 512 blocks, 64 thr
    for (int i = tid; i < 8 * G1_; i += 64) {
        int r = i >> 7, k = i & 127;
        fr[r][k] = fmaxf(g_h1[(r0 + r) * G1_ + k], 0.0f);
    }
    __syncthreads();
    const float* wr = w + tid * G1_;
    float acc[8] = {0, 0, 0, 0, 0, 0, 0, 0};
#pragma unroll 4
    for (int k = 0; k < G1_; k++) {
        float wk = wr[k];
#pragma unroll
        for (int r = 0; r < 8; r++) acc[r] = fmaf(fr[r][k], wk, acc[r]);
    }
    float bv = bias[tid];
#pragma unroll
    for (int r = 0; r < 8; r++) {
        g_xl2[(r0 + r) * G2_ + tid] = acc[r];
        float d = g_dis[(r0 + r) & (N_ - 1)];
        g_h2[(r0 + r) * G2_ + tid] = bv + acc[r] * d * d;
    }
}

template <int Gd>
__global__ void k_agg_edge(const void* __restrict__ ei) {
    constexpr int G4 = Gd / 4;
    const float* xl = (Gd == G1_) ? g_xl1 : g_xl2;
    float* outb     = (Gd == G1_) ? g_h1  : g_h2;
    int i = blockIdx.x * blockDim.x + threadIdx.x;
    constexpr int per = B_ * G4;
    if (i >= E_ * per) return;
    int e = i / per;
    int r = i - e * per;
    int b = r / G4;
    int g4 = r - b * G4;
    int is64 = g_is64;
    int src = edge_at(ei, is64, e);
    int dst = edge_at(ei, is64, E_ + e);
    float norm = g_dis[src] * g_dis[dst];
    float4 v = *(const float4*)&xl[(b * N_ + src) * Gd + g4 * 4];
    float* o = &outb[(b * N_ + dst) * Gd + g4 * 4];
    atomicAdd(o + 0, v.x * norm);
    atomicAdd(o + 1, v.y * norm);
    atomicAdd(o + 2, v.z * norm);
    atomicAdd(o + 3, v.w * norm);
}

__global__ void k_final(const float* __restrict__ cls_w,
                        const float* __restrict__ cls_b,
                        float* __restrict__ out) {
    int b = blockIdx.x, tid = threadIdx.x;
    __shared__ float red[256];
    float a = 0.0f;
    for (int i = tid; i < N_ * G2_; i += 256) {
        int g = i & (G2_ - 1);
        a = fmaf(fmaxf(g_h2[b * (N_ * G2_) + i], 0.0f), cls_w[g], a);
    }
    red[tid] = a;
    __syncthreads();
    for (int s = 128; s > 0; s >>= 1) {
        if (tid < s) red[tid] += red[tid + s];
        __syncthreads();
    }
    if (tid == 0) out[b] = red[0] * (1.0f / N_) + cls_b[0];
}

// ---------------- launch -----------------------------------------------------------
extern "C" void kernel_launch(void* const* d_in, const int* in_sizes, int n_in,
                              void* d_out, int out_size) {
    const float* x      = (const float*)d_in[0];
    const void*  ei     = d_in[1];
    const float* w_ih0  = (const float*)d_in[2];
    const float* w_hh0  = (const float*)d_in[3];
    const float* b_ih0  = (const float*)d_in[4];
    const float* b_hh0  = (const float*)d_in[5];
    const float* w_ih1  = (const float*)d_in[6];
    const float* w_hh1  = (const float*)d_in[7];
    const float* b_ih1  = (const float*)d_in[8];
    const float* b_hh1  = (const float*)d_in[9];
    const float* w_ih2  = (const float*)d_in[10];
    const float* w_hh2  = (const float*)d_in[11];
    const float* b_ih2  = (const float*)d_in[12];
    const float* b_hh2  = (const float*)d_in[13];
    const float* gcn1_w = (const float*)d_in[14];
    const float* gcn1_b = (const float*)d_in[15];
    const float* gcn2_w = (const float*)d_in[16];
    const float* gcn2_b = (const float*)d_in[17];
    const float* cls_w  = (const float*)d_in[18];
    const float* cls_b  = (const float*)d_in[19];
    float* out = (float*)d_out;

    u32 *whh, *wih;
    float *br, *w0r;
    cudaGetSymbolAddress((void**)&whh, g_whh_h);
    cudaGetSymbolAddress((void**)&wih, g_wih_h);
    cudaGetSymbolAddress((void**)&br, g_br);
    cudaGetSymbolAddress((void**)&w0r, g_w0r);

    cudaFuncSetAttribute(rec_mma<0, 1>, cudaFuncAttributeMaxDynamicSharedMemorySize, REC_SM);
    cudaFuncSetAttribute(rec_mma<1, 1>, cudaFuncAttributeMaxDynamicSharedMemorySize, REC_SM);
    cudaFuncSetAttribute(rec_mma<1, 0>, cudaFuncAttributeMaxDynamicSharedMemorySize, REC_SM);
    cudaFuncSetAttribute(proj_mma, cudaFuncAttributeMaxDynamicSharedMemorySize, PROJ_SM);

    constexpr int WN = G4H * 64;
    const int RB = S_ / 32;   // 128 blocks

    // layer 0
    k_edge_prep<<<1, 512>>>(ei);
    k_prep_w<<<WN / 256, 256>>>(w_hh0, whh + 0 * WN);
    k_prep_bw0<<<2, 256>>>(b_ih0, b_hh0, w_ih0);
    rec_mma<0, 1><<<RB, 512, REC_SM>>>(x, whh + 0 * WN, w0r, br + 0 * G4H);

    // layer 1
    k_prep_w<<<WN / 256, 256>>>(w_ih1, wih + 0 * WN);
    k_prep_b<<<2, 256>>>(b_ih1, b_hh1, br + 1 * G4H);
    proj_mma<<<148, 512, PROJ_SM>>>(wih + 0 * WN, br + 1 * G4H);
    k_prep_w<<<WN / 256, 256>>>(w_hh1, whh + 1 * WN);
    rec_mma<1, 1><<<RB, 512, REC_SM>>>(nullptr, whh + 1 * WN, nullptr, nullptr);

    // layer 2
    k_prep_w<<<WN / 256, 256>>>(w_ih2, wih + 1 * WN);
    k_prep_b<<<2, 256>>>(b_ih2, b_hh2, br + 2 * G4H);
    proj_mma<<<148, 512, PROJ_SM>>>(wih + 1 * WN, br + 2 * G4H);
    k_prep_w<<<WN / 256, 256>>>(w_hh2, whh + 2 * WN);
    rec_mma<1, 0><<<RB, 512, REC_SM>>>(nullptr, whh + 2 * WN, nullptr, nullptr);

    // GCN
    k_lin1<<<S_ / 8, 128>>>(gcn1_w, gcn1_b);
    k_agg_edge<G1_><<<(E_ * B_ * (G1_ / 4) + 255) / 256, 256>>>(ei);
    k_lin2<<<S_ / 8, 64>>>(gcn2_w, gcn2_b);
    k_agg_edge<G2_><<<(E_ * B_ * (G2_ / 4) + 255) / 256, 256>>>(ei);
    k_final<<<B_, 256>>>(cls_w, cls_b, out);
}